// round 2
// baseline (speedup 1.0000x reference)
#include <cuda_runtime.h>
#include <math.h>

#define NPTS 8192
#define NPB 4
#define LDM 68

__device__ float  g_t[(size_t)64 * NPTS * 64];
__device__ double g_sum[64], g_sumsq[64];
__device__ float  g_mean[64], g_istd[64];
__device__ float  g_pmax[8 * 64 * 64];

#define FMA4(a,s,v) {(a).x=fmaf((s),(v).x,(a).x);(a).y=fmaf((s),(v).y,(a).y);(a).z=fmaf((s),(v).z,(a).z);(a).w=fmaf((s),(v).w,(a).w);}

template<int K>
__device__ __forceinline__ void mm(const float* __restrict__ A, int lda,
                                   const float* __restrict__ Bm, int ldb,
                                   int r0, int c0, float4 acc[4]) {
    #pragma unroll
    for (int k = 0; k < K; ++k) {
        float4 w = *(const float4*)(Bm + k*ldb + c0);
        float a0 = A[(r0+0)*lda+k], a1 = A[(r0+1)*lda+k];
        float a2 = A[(r0+2)*lda+k], a3 = A[(r0+3)*lda+k];
        FMA4(acc[0],a0,w); FMA4(acc[1],a1,w); FMA4(acc[2],a2,w); FMA4(acc[3],a3,w);
    }
}

__global__ void zero_stats_k() {
    int t = threadIdx.x;
    if (t < 64) { g_sum[t] = 0.0; g_sumsq[t] = 0.0; }
}

__global__ __launch_bounds__(512, 1)
void phaseA_k(const float* __restrict__ x, const float* __restrict__ y,
              const float* __restrict__ Wl, const float* __restrict__ bl,
              const float* __restrict__ Wr, const float* __restrict__ br,
              const float* __restrict__ Wqk,
              const float* __restrict__ Wv, const float* __restrict__ bv,
              const float* __restrict__ Wt, const float* __restrict__ bt)
{
    extern __shared__ float sm[];
    float* s_Wl   = sm;               // [10][64]
    float* s_Wr   = s_Wl + 640;       // [13][64]
    float* s_WqkT = s_Wr + 832;       // [64][16]  WqkT[k][d]=Wqk[d][k]
    float* s_WvT  = s_WqkT + 1024;    // [64][64]  WvT[k][c]=Wv[c][k]
    float* s_WtT  = s_WvT + 4096;     // [64][64]  WtT[c][d]=Wt[d][c]
    float* s_bl   = s_WtT + 4096;
    float* s_br   = s_bl + 64;
    float* s_bv   = s_br + 64;
    float* s_bt   = s_bv + 64;
    float* s_cs   = s_bt + 64;
    float* s_cq   = s_cs + 64;
    float* grp    = s_cq + 64;
    const int GRP = 4*64*LDM + 2368 + 192;   // 19968 floats / group

    int tid = threadIdx.x;
    for (int i = tid; i < 640;  i += 512) s_Wl[i] = Wl[i];
    for (int i = tid; i < 832;  i += 512) s_Wr[i] = Wr[i];
    for (int i = tid; i < 1024; i += 512) { int d=i>>6, c=i&63; s_WqkT[c*16+d] = Wqk[i]; }
    for (int i = tid; i < 4096; i += 512) { int c=i>>6, k=i&63; s_WvT[k*64+c]  = Wv[i]; }
    for (int i = tid; i < 4096; i += 512) { int d=i>>6, c=i&63; s_WtT[c*64+d]  = Wt[i]; }
    if (tid < 64) { s_bl[tid]=bl[tid]; s_br[tid]=br[tid]; s_bv[tid]=bv[tid]; s_bt[tid]=bt[tid];
                    s_cs[tid]=0.f; s_cq[tid]=0.f; }
    __syncthreads();

    const int g = tid >> 8, u = tid & 255;
    float* s_X = grp + g*GRP;        // [64][LDM]
    float* s_Y = s_X + 64*LDM;
    float* s_A = s_Y + 64*LDM;
    float* s_Z = s_A + 64*LDM;
    float* s_R = s_Z + 64*LDM;       // union scratch (2368 floats)
    float* s_x   = s_R;              // [64][12]
    float* s_yb  = s_R + 768;        // [64][14]
    float* s_xq  = s_R;              // [64][20]  (reuse after X,Y built)
    float* s_ykT = s_R + 1280;       // [16][LDM]
    float* s_ri  = s_R + 2368;
    float* s_cr  = s_ri + 64;
    float* s_rs  = s_cr + 64;

    const int tr = u>>4, tc = u&15, r0 = tr*4, c0 = tc*4;
    const int qb = u>>2, q4 = (u&3)*4;
    float ts0=0,ts1=0,ts2=0,ts3=0, tq0=0,tq1=0,tq2=0,tq3=0;

    #pragma unroll 1
    for (int it = 0; it < NPB; ++it) {
        const int n = blockIdx.x*(2*NPB) + g*NPB + it;

        for (int i=u; i<640; i+=256) { int b=i/10, k=i-b*10; s_x[b*12+k]  = x[((size_t)b*NPTS+n)*10+k]; }
        for (int i=u; i<832; i+=256) { int b=i/13, k=i-b*13; s_yb[b*14+k] = y[((size_t)b*NPTS+n)*13+k]; }
        __syncthreads();

        // X = x@Wl + bl ; Y = y@Wr + br
        {
            float4 bb = *(const float4*)(s_bl+c0);
            float4 a[4] = {bb,bb,bb,bb};
            mm<10>(s_x, 12, s_Wl, 64, r0, c0, a);
            #pragma unroll
            for (int i=0;i<4;++i) *(float4*)(s_X+(r0+i)*LDM+c0) = a[i];
            bb = *(const float4*)(s_br+c0);
            float4 b2[4] = {bb,bb,bb,bb};
            mm<13>(s_yb, 14, s_Wr, 64, r0, c0, b2);
            #pragma unroll
            for (int i=0;i<4;++i) *(float4*)(s_Y+(r0+i)*LDM+c0) = b2[i];
        }
        __syncthreads();

        // xq = X@Wqk^T ; yk = Y@Wqk^T (yk stored transposed)
        {
            float4 aq = make_float4(0,0,0,0), ak = aq;
            #pragma unroll
            for (int k = 0; k < 64; ++k) {
                float4 w = *(const float4*)(s_WqkT + k*16 + q4);
                float xv = s_X[qb*LDM+k], yv2 = s_Y[qb*LDM+k];
                FMA4(aq, xv, w); FMA4(ak, yv2, w);
            }
            *(float4*)(s_xq + qb*20 + q4) = aq;
            s_ykT[(q4+0)*LDM+qb] = ak.x; s_ykT[(q4+1)*LDM+qb] = ak.y;
            s_ykT[(q4+2)*LDM+qb] = ak.z; s_ykT[(q4+3)*LDM+qb] = ak.w;
        }
        __syncthreads();

        // energy = xq @ yk^T
        {
            float4 z = make_float4(0,0,0,0);
            float4 a[4] = {z,z,z,z};
            mm<16>(s_xq, 20, s_ykT, LDM, r0, c0, a);
            #pragma unroll
            for (int i=0;i<4;++i) *(float4*)(s_A+(r0+i)*LDM+c0) = a[i];
        }
        __syncthreads();

        // row softmax (4 lanes/row)
        {
            int base = qb*LDM + (u&3)*16;
            float m = -1e30f;
            #pragma unroll
            for (int e=0;e<16;++e) m = fmaxf(m, s_A[base+e]);
            m = fmaxf(m, __shfl_xor_sync(~0u, m, 1));
            m = fmaxf(m, __shfl_xor_sync(~0u, m, 2));
            float ssum = 0.f;
            #pragma unroll
            for (int e=0;e<16;++e) { float v = __expf(s_A[base+e]-m); s_A[base+e]=v; ssum+=v; }
            ssum += __shfl_xor_sync(~0u, ssum, 1);
            ssum += __shfl_xor_sync(~0u, ssum, 2);
            if ((u&3)==0) s_ri[qb] = 1.0f/ssum;
        }
        __syncthreads();
        if (u < 64) {   // column sums over b of row-normalized attn
            float cs = 0.f;
            #pragma unroll 8
            for (int b=0;b<64;++b) cs = fmaf(s_A[b*LDM+u], s_ri[b], cs);
            s_cr[u] = 1.0f/(1e-9f+cs);
        }
        __syncthreads();
        {   // renormalize + row sums
            int base = qb*LDM + (u&3)*16;
            float ri = s_ri[qb], rv = 0.f;
            #pragma unroll
            for (int e=0;e<16;++e) {
                float a = s_A[base+e]*ri*s_cr[(u&3)*16+e];
                s_A[base+e] = a; rv += a;
            }
            rv += __shfl_xor_sync(~0u, rv, 1);
            rv += __shfl_xor_sync(~0u, rv, 2);
            if ((u&3)==0) s_rs[qb] = rv;
        }
        __syncthreads();

        // Z = attn @ Y
        {
            float4 z = make_float4(0,0,0,0);
            float4 a[4] = {z,z,z,z};
            mm<64>(s_A, LDM, s_Y, LDM, r0, c0, a);
            #pragma unroll
            for (int i=0;i<4;++i) *(float4*)(s_Z+(r0+i)*LDM+c0) = a[i];
        }
        __syncthreads();

        // U = X - (Z@Wv^T + rowsum*b_v)  -> overwrite s_A
        {
            float4 bb = *(const float4*)(s_bv+c0);
            float4 a[4];
            #pragma unroll
            for (int i=0;i<4;++i) { float r = s_rs[r0+i];
                a[i] = make_float4(bb.x*r, bb.y*r, bb.z*r, bb.w*r); }
            mm<64>(s_Z, LDM, s_WvT, 64, r0, c0, a);
            #pragma unroll
            for (int i=0;i<4;++i) {
                float4 xv = *(const float4*)(s_X+(r0+i)*LDM+c0);
                a[i].x = xv.x-a[i].x; a[i].y = xv.y-a[i].y;
                a[i].z = xv.z-a[i].z; a[i].w = xv.w-a[i].w;
                *(float4*)(s_A+(r0+i)*LDM+c0) = a[i];
            }
        }
        __syncthreads();

        // t = U@Wt^T + bt -> global scratch + channel stats
        {
            float4 bb = *(const float4*)(s_bt+c0);
            float4 a[4] = {bb,bb,bb,bb};
            mm<64>(s_A, LDM, s_WtT, 64, r0, c0, a);
            #pragma unroll
            for (int i=0;i<4;++i) {
                *(float4*)(&g_t[(((size_t)(r0+i))*NPTS+n)*64 + c0]) = a[i];
                ts0+=a[i].x; tq0+=a[i].x*a[i].x; ts1+=a[i].y; tq1+=a[i].y*a[i].y;
                ts2+=a[i].z; tq2+=a[i].z*a[i].z; ts3+=a[i].w; tq3+=a[i].w*a[i].w;
            }
        }
        __syncthreads();
    }

    atomicAdd(&s_cs[c0+0], ts0); atomicAdd(&s_cq[c0+0], tq0);
    atomicAdd(&s_cs[c0+1], ts1); atomicAdd(&s_cq[c0+1], tq1);
    atomicAdd(&s_cs[c0+2], ts2); atomicAdd(&s_cq[c0+2], tq2);
    atomicAdd(&s_cs[c0+3], ts3); atomicAdd(&s_cq[c0+3], tq3);
    __syncthreads();
    if (tid < 64) {
        atomicAdd(&g_sum[tid],   (double)s_cs[tid]);
        atomicAdd(&g_sumsq[tid], (double)s_cq[tid]);
    }
}

__global__ void stats_fin_k() {
    int c = threadIdx.x;
    if (c < 64) {
        double M = (double)64 * NPTS;
        double mu = g_sum[c] / M;
        double var = g_sumsq[c] / M - mu*mu;
        g_mean[c] = (float)mu;
        g_istd[c] = rsqrtf((float)var + 1e-5f);
    }
}

__global__ __launch_bounds__(256)
void phaseB_k(const float* __restrict__ x, const float* __restrict__ Wl,
              const float* __restrict__ bl, const float* __restrict__ gamma,
              const float* __restrict__ beta)
{
    int b = blockIdx.x, ch = blockIdx.y;
    int c = threadIdx.x & 63, lane = threadIdx.x >> 6;
    __shared__ float s_w[640];
    __shared__ float s_red[4][64];
    for (int i = threadIdx.x; i < 640; i += 256) s_w[i] = Wl[i];
    __syncthreads();
    float wl[10];
    #pragma unroll
    for (int k=0;k<10;++k) wl[k] = s_w[k*64+c];
    float blc = bl[c], ga = gamma[c], be = beta[c], mu = g_mean[c], is = g_istd[c];
    float mx = -1e30f;
    int n0 = ch*1024, n1 = n0+1024;
    #pragma unroll 4
    for (int n = n0+lane; n < n1; n += 4) {
        const float* xp = &x[((size_t)b*NPTS+n)*10];
        float X = blc;
        #pragma unroll
        for (int k=0;k<10;++k) X = fmaf(xp[k], wl[k], X);
        float t = g_t[(((size_t)b)*NPTS+n)*64 + c];
        float tn = fmaf(ga, (t-mu)*is, be);
        mx = fmaxf(mx, X + fmaxf(tn, 0.f));
    }
    s_red[lane][c] = mx;
    __syncthreads();
    if (threadIdx.x < 64) {
        float m = fmaxf(fmaxf(s_red[0][c], s_red[1][c]), fmaxf(s_red[2][c], s_red[3][c]));
        g_pmax[(ch*64 + b)*64 + c] = m;
    }
}

__global__ void final_red_k(float* __restrict__ out) {
    int i = blockIdx.x*256 + threadIdx.x;   // i = b*64+c
    if (i < 4096) {
        float m = -1e30f;
        #pragma unroll
        for (int ch=0; ch<8; ++ch) m = fmaxf(m, g_pmax[ch*4096 + i]);
        out[i] = m;
    }
}

extern "C" void kernel_launch(void* const* d_in, const int* in_sizes, int n_in,
                              void* d_out, int out_size) {
    const float* x    = (const float*)d_in[0];
    const float* y    = (const float*)d_in[1];
    const float* Wl   = (const float*)d_in[2];
    const float* bl   = (const float*)d_in[3];
    const float* Wr   = (const float*)d_in[4];
    const float* br   = (const float*)d_in[5];
    const float* Wqk  = (const float*)d_in[6];
    const float* Wv   = (const float*)d_in[7];
    const float* bv   = (const float*)d_in[8];
    const float* Wt   = (const float*)d_in[9];
    const float* bt   = (const float*)d_in[10];
    const float* gamma= (const float*)d_in[11];
    const float* beta = (const float*)d_in[12];
    float* out = (float*)d_out;

    const int smem = (11072 + 2*(4*64*LDM + 2368 + 192)) * 4;
    cudaFuncSetAttribute(phaseA_k, cudaFuncAttributeMaxDynamicSharedMemorySize, smem);

    zero_stats_k<<<1, 64>>>();
    phaseA_k<<<NPTS/(2*NPB), 512, smem>>>(x, y, Wl, bl, Wr, br, Wqk, Wv, bv, Wt, bt);
    stats_fin_k<<<1, 64>>>();
    dim3 gB(64, 8);
    phaseB_k<<<gB, 256>>>(x, Wl, bl, gamma, beta);
    final_red_k<<<16, 256>>>(out);
}

// round 3
// speedup vs baseline: 1.4117x; 1.4117x over previous
#include <cuda_runtime.h>
#include <math.h>

#define NPTS 8192
#define NPB  4
#define LDA_ 68   // A-operand arrays (ld % 32 == 4): conflict-free A-fragment gathers
#define LDB_ 72   // B-only arrays    (ld % 32 == 8): conflict-free B-fragment gathers
#define LDQ  20
#define LDW  24

__device__ float  g_t[(size_t)64 * NPTS * 64];
__device__ double g_sum[64], g_sumsq[64];
__device__ float  g_mean[64], g_istd[64];
__device__ float  g_pmax[16 * 64 * 64];

#define FMA4(a,s,v) {(a).x=fmaf((s),(v).x,(a).x);(a).y=fmaf((s),(v).y,(a).y);(a).z=fmaf((s),(v).z,(a).z);(a).w=fmaf((s),(v).w,(a).w);}

__device__ __forceinline__ float tf32r(float x) {
    unsigned u; asm("cvt.rna.tf32.f32 %0, %1;" : "=r"(u) : "f"(x));
    return __uint_as_float(u);
}

__device__ __forceinline__ void mma8(float4& c, const float a[4], float b0, float b1) {
    asm volatile("mma.sync.aligned.m16n8k8.row.col.f32.tf32.tf32.f32 "
        "{%0,%1,%2,%3},{%4,%5,%6,%7},{%8,%9},{%0,%1,%2,%3};"
        : "+f"(c.x), "+f"(c.y), "+f"(c.z), "+f"(c.w)
        : "r"(__float_as_uint(a[0])), "r"(__float_as_uint(a[1])),
          "r"(__float_as_uint(a[2])), "r"(__float_as_uint(a[3])),
          "r"(__float_as_uint(b0)),  "r"(__float_as_uint(b1)));
}

__device__ __forceinline__ void barg(int id) {
    asm volatile("bar.sync %0, 256;" :: "r"(id) : "memory");
}

// 64x32 warp tile: A[m0..m0+16) x B cols [n0..n0+32), K in steps of 8
template<int K, int LDAv, int LDBv>
__device__ __forceinline__ void mma_gemm(const float* __restrict__ A, const float* __restrict__ B,
                                         int m0, int n0, int fg, int ft, float4 acc[4]) {
    #pragma unroll
    for (int k0 = 0; k0 < K; k0 += 8) {
        float a[4];
        a[0] = A[(m0+fg  )*LDAv + k0+ft  ];
        a[1] = A[(m0+fg+8)*LDAv + k0+ft  ];
        a[2] = A[(m0+fg  )*LDAv + k0+ft+4];
        a[3] = A[(m0+fg+8)*LDAv + k0+ft+4];
        #pragma unroll
        for (int j = 0; j < 4; ++j)
            mma8(acc[j], a, B[(k0+ft)*LDBv + n0+8*j+fg], B[(k0+ft+4)*LDBv + n0+8*j+fg]);
    }
}

template<int K>
__device__ __forceinline__ void mm(const float* __restrict__ A, int lda,
                                   const float* __restrict__ Bm, int ldb,
                                   int r0, int c0, float4 acc[4]) {
    #pragma unroll
    for (int k = 0; k < K; ++k) {
        float4 w = *(const float4*)(Bm + k*ldb + c0);
        float a0 = A[(r0+0)*lda+k], a1 = A[(r0+1)*lda+k];
        float a2 = A[(r0+2)*lda+k], a3 = A[(r0+3)*lda+k];
        FMA4(acc[0],a0,w); FMA4(acc[1],a1,w); FMA4(acc[2],a2,w); FMA4(acc[3],a3,w);
    }
}

__global__ void zero_stats_k() {
    int t = threadIdx.x;
    if (t < 64) { g_sum[t] = 0.0; g_sumsq[t] = 0.0; }
}

__global__ __launch_bounds__(512, 1)
void phaseA_k(const float* __restrict__ x, const float* __restrict__ y,
              const float* __restrict__ Wl, const float* __restrict__ bl,
              const float* __restrict__ Wr, const float* __restrict__ br,
              const float* __restrict__ Wqk,
              const float* __restrict__ Wv, const float* __restrict__ bv,
              const float* __restrict__ Wt, const float* __restrict__ bt)
{
    extern __shared__ float sm[];
    float* s_Wl  = sm;                 // 640  fp32
    float* s_Wr  = s_Wl  + 640;       // 832  fp32
    float* s_Wqk = s_Wr  + 832;       // [64][LDW] tf32: [c][d] = Wqk[d][c]
    float* s_WvT = s_Wqk + 64*LDW;    // [64][LDB_] tf32: [k][c] = Wv[c][k]
    float* s_WtT = s_WvT + 64*LDB_;   // [64][LDB_] tf32: [c][d] = Wt[d][c]
    float* s_bl  = s_WtT + 64*LDB_;
    float* s_br  = s_bl + 64;
    float* s_bv  = s_br + 64;
    float* s_bt  = s_bv + 64;
    float* s_cs  = s_bt + 64;
    float* s_cq  = s_cs + 64;
    float* grp   = s_cq + 64;
    const int GRP = 64*LDA_*3 + 64*LDB_ + 2368 + 192;

    int tid = threadIdx.x;
    for (int i = tid; i < 640;  i += 512) s_Wl[i] = Wl[i];
    for (int i = tid; i < 832;  i += 512) s_Wr[i] = Wr[i];
    for (int i = tid; i < 1024; i += 512) { int d=i>>6, c=i&63; s_Wqk[c*LDW+d]  = tf32r(Wqk[i]); }
    for (int i = tid; i < 4096; i += 512) { int c=i>>6, k=i&63; s_WvT[k*LDB_+c] = tf32r(Wv[i]); }
    for (int i = tid; i < 4096; i += 512) { int d=i>>6, c=i&63; s_WtT[c*LDB_+d] = tf32r(Wt[i]); }
    if (tid < 64) { s_bl[tid]=bl[tid]; s_br[tid]=br[tid]; s_bv[tid]=bv[tid]; s_bt[tid]=bt[tid];
                    s_cs[tid]=0.f; s_cq[tid]=0.f; }
    __syncthreads();

    const int gg = tid >> 8, u = tid & 255;
    const int bid = gg + 1;
    float* s_X = grp + gg*GRP;         // [64][LDA_] tf32
    float* s_Y = s_X + 64*LDA_;        // [64][LDB_] tf32
    float* s_A = s_Y + 64*LDB_;        // [64][LDA_] energy(fp32)->attn(tf32)->U(tf32)
    float* s_Z = s_A + 64*LDA_;        // [64][LDA_] Z(tf32) / t staging (fp32)
    float* s_R = s_Z + 64*LDA_;        // union 2368
    float* s_x   = s_R;                // [64][12]
    float* s_yb  = s_R + 768;          // [64][14]
    float* s_xq  = s_R;                // [64][LDQ] tf32
    float* s_ykT = s_R + 1280;         // [16][LDA_] tf32
    float* s_ri  = s_R + 2368;
    float* s_cr  = s_ri + 64;
    float* s_rs  = s_cr + 64;

    const int tr = u>>4, tc = u&15, r0 = tr*4, c0 = tc*4;
    const int qb = u>>2;
    const int w = u>>5, lane = u&31, fg = lane>>2, ft = lane&3;
    const int wm0 = (w&3)*16, wn0 = (w>>2)*32;

    float ts[8] = {0,0,0,0,0,0,0,0}, tq[8] = {0,0,0,0,0,0,0,0};

    #pragma unroll 1
    for (int it = 0; it < NPB; ++it) {
        const int n = blockIdx.x*(2*NPB) + gg*NPB + it;

        for (int i=u; i<640; i+=256) { int b=i/10, k=i-b*10; s_x[b*12+k]  = x[((size_t)b*NPTS+n)*10+k]; }
        for (int i=u; i<832; i+=256) { int b=i/13, k=i-b*13; s_yb[b*14+k] = y[((size_t)b*NPTS+n)*13+k]; }
        barg(bid);

        // X = x@Wl + bl ; Y = y@Wr + br  (fp32 SIMT, stored tf32-rounded)
        {
            float4 bb = *(const float4*)(s_bl+c0);
            float4 a[4] = {bb,bb,bb,bb};
            mm<10>(s_x, 12, s_Wl, 64, r0, c0, a);
            #pragma unroll
            for (int i=0;i<4;++i) {
                float4 o = make_float4(tf32r(a[i].x),tf32r(a[i].y),tf32r(a[i].z),tf32r(a[i].w));
                *(float4*)(s_X+(r0+i)*LDA_+c0) = o;
            }
            bb = *(const float4*)(s_br+c0);
            float4 b2[4] = {bb,bb,bb,bb};
            mm<13>(s_yb, 14, s_Wr, 64, r0, c0, b2);
            #pragma unroll
            for (int i=0;i<4;++i) {
                float4 o = make_float4(tf32r(b2[i].x),tf32r(b2[i].y),tf32r(b2[i].z),tf32r(b2[i].w));
                *(float4*)(s_Y+(r0+i)*LDB_+c0) = o;
            }
        }
        barg(bid);

        // G1: [X;Y](128x64) @ WqkT(64x16) -> xq [b][d], ykT [d][e]
        {
            const float* A = (w < 4) ? (s_X + (w*16)*LDA_) : (s_Y + ((w-4)*16)*LDB_);
            const int lda = (w < 4) ? LDA_ : LDB_;
            float4 acc0 = make_float4(0,0,0,0), acc1 = acc0;
            #pragma unroll
            for (int k0 = 0; k0 < 64; k0 += 8) {
                float a[4];
                a[0] = A[fg*lda + k0+ft];   a[1] = A[(fg+8)*lda + k0+ft];
                a[2] = A[fg*lda + k0+ft+4]; a[3] = A[(fg+8)*lda + k0+ft+4];
                mma8(acc0, a, s_Wqk[(k0+ft)*LDW + fg],   s_Wqk[(k0+ft+4)*LDW + fg]);
                mma8(acc1, a, s_Wqk[(k0+ft)*LDW + 8+fg], s_Wqk[(k0+ft+4)*LDW + 8+fg]);
            }
            if (w < 4) {
                int r = w*16+fg, c = 2*ft;
                *(float2*)&s_xq[r*LDQ + c]         = make_float2(tf32r(acc0.x), tf32r(acc0.y));
                *(float2*)&s_xq[(r+8)*LDQ + c]     = make_float2(tf32r(acc0.z), tf32r(acc0.w));
                *(float2*)&s_xq[r*LDQ + 8+c]       = make_float2(tf32r(acc1.x), tf32r(acc1.y));
                *(float2*)&s_xq[(r+8)*LDQ + 8+c]   = make_float2(tf32r(acc1.z), tf32r(acc1.w));
            } else {
                int e = (w-4)*16+fg, d0 = 2*ft;
                s_ykT[ d0   *LDA_ + e  ] = tf32r(acc0.x); s_ykT[(d0+1)*LDA_ + e  ] = tf32r(acc0.y);
                s_ykT[ d0   *LDA_ + e+8] = tf32r(acc0.z); s_ykT[(d0+1)*LDA_ + e+8] = tf32r(acc0.w);
                s_ykT[(8+d0)*LDA_ + e  ] = tf32r(acc1.x); s_ykT[(9+d0)*LDA_ + e  ] = tf32r(acc1.y);
                s_ykT[(8+d0)*LDA_ + e+8] = tf32r(acc1.z); s_ykT[(9+d0)*LDA_ + e+8] = tf32r(acc1.w);
            }
        }
        barg(bid);

        // G2: energy = xq(64x16) @ ykT -> s_A fp32
        {
            float4 acc[4] = {make_float4(0,0,0,0),make_float4(0,0,0,0),make_float4(0,0,0,0),make_float4(0,0,0,0)};
            mma_gemm<16, LDQ, LDA_>(s_xq, s_ykT, wm0, wn0, fg, ft, acc);
            #pragma unroll
            for (int j = 0; j < 4; ++j) {
                int col = wn0 + 8*j + 2*ft;
                *(float2*)&s_A[(wm0+fg  )*LDA_ + col] = make_float2(acc[j].x, acc[j].y);
                *(float2*)&s_A[(wm0+fg+8)*LDA_ + col] = make_float2(acc[j].z, acc[j].w);
            }
        }
        barg(bid);

        // softmax rows
        {
            int base = qb*LDA_ + (u&3)*16;
            float m = -1e30f;
            #pragma unroll
            for (int e=0;e<16;++e) m = fmaxf(m, s_A[base+e]);
            m = fmaxf(m, __shfl_xor_sync(~0u, m, 1));
            m = fmaxf(m, __shfl_xor_sync(~0u, m, 2));
            float ssum = 0.f;
            #pragma unroll
            for (int e=0;e<16;++e) { float v = __expf(s_A[base+e]-m); s_A[base+e]=v; ssum+=v; }
            ssum += __shfl_xor_sync(~0u, ssum, 1);
            ssum += __shfl_xor_sync(~0u, ssum, 2);
            if ((u&3)==0) s_ri[qb] = 1.0f/ssum;
        }
        barg(bid);
        if (u < 64) {
            float cs = 0.f;
            #pragma unroll 8
            for (int b=0;b<64;++b) cs = fmaf(s_A[b*LDA_+u], s_ri[b], cs);
            s_cr[u] = 1.0f/(1e-9f+cs);
        }
        barg(bid);
        {
            int base = qb*LDA_ + (u&3)*16;
            float ri = s_ri[qb], rv = 0.f;
            #pragma unroll
            for (int e=0;e<16;++e) {
                float a = s_A[base+e]*ri*s_cr[(u&3)*16+e];
                s_A[base+e] = tf32r(a); rv += a;
            }
            rv += __shfl_xor_sync(~0u, rv, 1);
            rv += __shfl_xor_sync(~0u, rv, 2);
            if ((u&3)==0) s_rs[qb] = rv;
        }
        barg(bid);

        // G3: Z = attn @ Y -> s_Z tf32
        {
            float4 acc[4] = {make_float4(0,0,0,0),make_float4(0,0,0,0),make_float4(0,0,0,0),make_float4(0,0,0,0)};
            mma_gemm<64, LDA_, LDB_>(s_A, s_Y, wm0, wn0, fg, ft, acc);
            #pragma unroll
            for (int j = 0; j < 4; ++j) {
                int col = wn0 + 8*j + 2*ft;
                *(float2*)&s_Z[(wm0+fg  )*LDA_ + col] = make_float2(tf32r(acc[j].x), tf32r(acc[j].y));
                *(float2*)&s_Z[(wm0+fg+8)*LDA_ + col] = make_float2(tf32r(acc[j].z), tf32r(acc[j].w));
            }
        }
        barg(bid);

        // G4: U = X - (Z@WvT + rowsum*bv) -> s_A tf32
        {
            float rsa = s_rs[wm0+fg], rsb = s_rs[wm0+fg+8];
            float4 acc[4];
            #pragma unroll
            for (int j = 0; j < 4; ++j) {
                int col = wn0 + 8*j + 2*ft;
                float bv0 = s_bv[col], bv1 = s_bv[col+1];
                acc[j] = make_float4(rsa*bv0, rsa*bv1, rsb*bv0, rsb*bv1);
            }
            mma_gemm<64, LDA_, LDB_>(s_Z, s_WvT, wm0, wn0, fg, ft, acc);
            #pragma unroll
            for (int j = 0; j < 4; ++j) {
                int col = wn0 + 8*j + 2*ft;
                float2 x0 = *(const float2*)&s_X[(wm0+fg  )*LDA_ + col];
                float2 x1 = *(const float2*)&s_X[(wm0+fg+8)*LDA_ + col];
                *(float2*)&s_A[(wm0+fg  )*LDA_ + col] = make_float2(tf32r(x0.x-acc[j].x), tf32r(x0.y-acc[j].y));
                *(float2*)&s_A[(wm0+fg+8)*LDA_ + col] = make_float2(tf32r(x1.x-acc[j].z), tf32r(x1.y-acc[j].w));
            }
        }
        barg(bid);

        // G5: t = U@WtT + bt -> stats + staging (s_Z fp32)
        {
            float4 acc[4];
            #pragma unroll
            for (int j = 0; j < 4; ++j) {
                int col = wn0 + 8*j + 2*ft;
                float b0 = s_bt[col], b1 = s_bt[col+1];
                acc[j] = make_float4(b0, b1, b0, b1);
            }
            mma_gemm<64, LDA_, LDB_>(s_A, s_WtT, wm0, wn0, fg, ft, acc);
            #pragma unroll
            for (int j = 0; j < 4; ++j) {
                int col = wn0 + 8*j + 2*ft;
                ts[2*j]   += acc[j].x + acc[j].z;
                tq[2*j]   += acc[j].x*acc[j].x + acc[j].z*acc[j].z;
                ts[2*j+1] += acc[j].y + acc[j].w;
                tq[2*j+1] += acc[j].y*acc[j].y + acc[j].w*acc[j].w;
                *(float2*)&s_Z[(wm0+fg  )*LDA_ + col] = make_float2(acc[j].x, acc[j].y);
                *(float2*)&s_Z[(wm0+fg+8)*LDA_ + col] = make_float2(acc[j].z, acc[j].w);
            }
        }
        barg(bid);

        // coalesced copy of t tile to gmem
        {
            int br = u>>2, cc = (u&3)*16;
            float* dst = &g_t[((size_t)br*NPTS + n)*64 + cc];
            const float* src = &s_Z[br*LDA_ + cc];
            #pragma unroll
            for (int q = 0; q < 4; ++q) *(float4*)(dst + 4*q) = *(const float4*)(src + 4*q);
        }
        barg(bid);
    }

    #pragma unroll
    for (int j = 0; j < 4; ++j) {
        int col = wn0 + 8*j + 2*ft;
        atomicAdd(&s_cs[col],   ts[2*j]);   atomicAdd(&s_cq[col],   tq[2*j]);
        atomicAdd(&s_cs[col+1], ts[2*j+1]); atomicAdd(&s_cq[col+1], tq[2*j+1]);
    }
    __syncthreads();
    if (tid < 64) {
        atomicAdd(&g_sum[tid],   (double)s_cs[tid]);
        atomicAdd(&g_sumsq[tid], (double)s_cq[tid]);
    }
}

__global__ void stats_fin_k() {
    int c = threadIdx.x;
    if (c < 64) {
        double M = (double)64 * NPTS;
        double mu = g_sum[c] / M;
        double var = g_sumsq[c] / M - mu*mu;
        g_mean[c] = (float)mu;
        g_istd[c] = rsqrtf((float)var + 1e-5f);
    }
}

__global__ __launch_bounds__(256)
void phaseB_k(const float* __restrict__ x, const float* __restrict__ Wl,
              const float* __restrict__ bl, const float* __restrict__ gamma,
              const float* __restrict__ beta)
{
    int b = blockIdx.x, ch = blockIdx.y;     // 64 x 16
    int tid = threadIdx.x;
    int cq = tid & 15, c0 = cq*4, nl = tid >> 4;
    __shared__ float s_w[640];
    __shared__ float s_x[1280];
    __shared__ float s_red[16][64];
    for (int i = tid; i < 640; i += 256) s_w[i] = Wl[i];
    __syncthreads();
    float4 wl4[10];
    #pragma unroll
    for (int k=0;k<10;++k) wl4[k] = *(const float4*)&s_w[k*64 + c0];
    float4 blv = *(const float4*)&bl[c0];
    float4 ga  = *(const float4*)&gamma[c0];
    float4 be  = *(const float4*)&beta[c0];
    float4 mu  = *(const float4*)&g_mean[c0];
    float4 is  = *(const float4*)&g_istd[c0];
    float4 sc, sh;
    sc.x = ga.x*is.x; sh.x = be.x - mu.x*sc.x;
    sc.y = ga.y*is.y; sh.y = be.y - mu.y*sc.y;
    sc.z = ga.z*is.z; sh.z = be.z - mu.z*sc.z;
    sc.w = ga.w*is.w; sh.w = be.w - mu.w*sc.w;
    float4 mx = make_float4(-3e38f,-3e38f,-3e38f,-3e38f);
    int n0 = ch*512;
    for (int chunk = 0; chunk < 4; ++chunk) {
        __syncthreads();
        const float4* xsrc = (const float4*)(x + ((size_t)b*NPTS + n0 + chunk*128)*10);
        for (int i = tid; i < 320; i += 256) ((float4*)s_x)[i] = xsrc[i];
        __syncthreads();
        #pragma unroll
        for (int i8 = 0; i8 < 8; ++i8) {
            int ln = nl + i8*16;
            int n = n0 + chunk*128 + ln;
            float4 tv = *(const float4*)&g_t[((size_t)b*NPTS+n)*64 + c0];
            const float* xr = &s_x[ln*10];
            float4 X = blv;
            #pragma unroll
            for (int k=0;k<10;++k) FMA4(X, xr[k], wl4[k]);
            float4 tn;
            tn.x = fmaxf(fmaf(tv.x, sc.x, sh.x), 0.f);
            tn.y = fmaxf(fmaf(tv.y, sc.y, sh.y), 0.f);
            tn.z = fmaxf(fmaf(tv.z, sc.z, sh.z), 0.f);
            tn.w = fmaxf(fmaf(tv.w, sc.w, sh.w), 0.f);
            mx.x = fmaxf(mx.x, X.x + tn.x);
            mx.y = fmaxf(mx.y, X.y + tn.y);
            mx.z = fmaxf(mx.z, X.z + tn.z);
            mx.w = fmaxf(mx.w, X.w + tn.w);
        }
    }
    *(float4*)&s_red[nl][c0] = mx;
    __syncthreads();
    if (tid < 64) {
        float m = s_red[0][tid];
        #pragma unroll
        for (int k=1;k<16;++k) m = fmaxf(m, s_red[k][tid]);
        g_pmax[((ch<<6)+b)*64 + tid] = m;
    }
}

__global__ void final_red_k(float* __restrict__ out) {
    int i = blockIdx.x*256 + threadIdx.x;
    if (i < 4096) {
        float m = -3e38f;
        #pragma unroll
        for (int ch=0; ch<16; ++ch) m = fmaxf(m, g_pmax[ch*4096 + i]);
        out[i] = m;
    }
}

extern "C" void kernel_launch(void* const* d_in, const int* in_sizes, int n_in,
                              void* d_out, int out_size) {
    const float* x    = (const float*)d_in[0];
    const float* y    = (const float*)d_in[1];
    const float* Wl   = (const float*)d_in[2];
    const float* bl   = (const float*)d_in[3];
    const float* Wr   = (const float*)d_in[4];
    const float* br   = (const float*)d_in[5];
    const float* Wqk  = (const float*)d_in[6];
    const float* Wv   = (const float*)d_in[7];
    const float* bv   = (const float*)d_in[8];
    const float* Wt   = (const float*)d_in[9];
    const float* bt   = (const float*)d_in[10];
    const float* gamma= (const float*)d_in[11];
    const float* beta = (const float*)d_in[12];
    float* out = (float*)d_out;

    const int weights = 640 + 832 + 64*LDW + 2*64*LDB_ + 4*64 + 2*64;
    const int GRP = 64*LDA_*3 + 64*LDB_ + 2368 + 192;
    const int smem = (weights + 2*GRP) * 4;
    cudaFuncSetAttribute(phaseA_k, cudaFuncAttributeMaxDynamicSharedMemorySize, smem);

    zero_stats_k<<<1, 64>>>();
    phaseA_k<<<NPTS/(2*NPB), 512, smem>>>(x, y, Wl, bl, Wr, br, Wqk, Wv, bv, Wt, bt);
    stats_fin_k<<<1, 64>>>();
    dim3 gB(64, 16);
    phaseB_k<<<gB, 256>>>(x, Wl, bl, gamma, beta);
    final_red_k<<<16, 256>>>(out);
}